// round 9
// baseline (speedup 1.0000x reference)
#include <cuda_runtime.h>
#include <cuda_fp16.h>
#include <cstdint>

// ===========================================================================
// BitNetSummaryEncoder — HMMA, register-resident W (fp16), fp16 A,
// z held in REGISTERS across the LN barrier (no zbuf staging).
//   16 warps; warp w owns output cols [16w,16w+16) (h and g).
//   Tile = 512 rows (phase0); LN in 8 subtiles of 64 rows.
//   1-term:  A_fp16 * W_fp16  (rel_err ~3e-4 < 1e-3 gate)
// ===========================================================================

#define THREADS       512
#define ROWS_PER_CTA  512
#define SUB_ROWS      64

__device__ float d_q[848];    // quantized ternary weights

// ---------------- smem layout (bytes) --------------------------------------
// init:  [0,65536) = W fp16 (frag load only, then reused as A)
#define SM_A    0u
#define SM_WH   0u
#define SM_RED  65536u        // 64 rows x 17 float2 = 8704
#define SM_STAT 74240u        // 64 x float2 = 512
#define SM_PAR  74752u        // params (float offsets below)
#define P_CEMB  0
#define P_REMB  320
#define P_Q     640
#define P_SB    1488
#define P_LNG   1552
#define P_LNB   1808
#define P_END   2064
#define SMEM_BYTES (SM_PAR + P_END * 4)   // 83008

// ---------------- PTX helpers -----------------------------------------------
__device__ __forceinline__ uint32_t smem_u32(const void* p) {
    uint32_t a;
    asm("{ .reg .u64 t; cvta.to.shared.u64 t, %1; cvt.u32.u64 %0, t; }"
        : "=r"(a) : "l"(p));
    return a;
}
__device__ __forceinline__ void ldsm_x4(uint32_t* r, uint32_t addr) {
    asm volatile("ldmatrix.sync.aligned.m8n8.x4.shared.b16 {%0,%1,%2,%3}, [%4];"
                 : "=r"(r[0]), "=r"(r[1]), "=r"(r[2]), "=r"(r[3]) : "r"(addr));
}
__device__ __forceinline__ void ldsm_x4t(uint32_t* r, uint32_t addr) {
    asm volatile("ldmatrix.sync.aligned.m8n8.x4.trans.shared.b16 {%0,%1,%2,%3}, [%4];"
                 : "=r"(r[0]), "=r"(r[1]), "=r"(r[2]), "=r"(r[3]) : "r"(addr));
}
__device__ __forceinline__ void mma16816(float* d, const uint32_t* a,
                                         const uint32_t* b) {
    asm volatile(
        "mma.sync.aligned.m16n8k16.row.col.f32.f16.f16.f32 "
        "{%0,%1,%2,%3}, {%4,%5,%6,%7}, {%8,%9}, {%0,%1,%2,%3};"
        : "+f"(d[0]), "+f"(d[1]), "+f"(d[2]), "+f"(d[3])
        : "r"(a[0]), "r"(a[1]), "r"(a[2]), "r"(a[3]), "r"(b[0]), "r"(b[1]));
}
__device__ __forceinline__ float gelu_exact(float x) {
    return 0.5f * x * (1.0f + erff(x * 0.7071067811865476f));
}
__device__ __forceinline__ uint32_t pack2h(float a, float b) {
    __half h0 = __float2half_rn(a);
    __half h1 = __float2half_rn(b);
    return (uint32_t)__half_as_ushort(h0) | ((uint32_t)__half_as_ushort(h1) << 16);
}
__device__ __forceinline__ float fast_glu(float h, float g) {
    return __fdividef(h, 1.0f + __expf(-g));
}

// ---------------------------------------------------------------------------
__global__ void quant_prep_kernel(const float* __restrict__ vw1,
                                  const float* __restrict__ vw2,
                                  const float* __restrict__ pw1,
                                  const float* __restrict__ pw2) {
    __shared__ float red[512];
    const float* W; int n; float* out;
    switch (blockIdx.x) {
        case 0:  W = vw1; n = 32;  out = d_q;       break;
        case 1:  W = vw2; n = 48;  out = d_q + 32;  break;
        case 2:  W = pw1; n = 288; out = d_q + 80;  break;
        default: W = pw2; n = 480; out = d_q + 368; break;
    }
    int t = threadIdx.x;
    red[t] = (t < n) ? fabsf(W[t]) : 0.0f;
    __syncthreads();
#pragma unroll
    for (int s = 256; s > 0; s >>= 1) {
        if (t < s) red[t] += red[t + s];
        __syncthreads();
    }
    float scale = red[0] / (float)n;
    if (t < n) {
        float q = rintf(W[t] / (scale + 1e-5f));
        q = fminf(fmaxf(q, -1.0f), 1.0f);
        out[t] = q * scale;
    }
}

// ---------------------------------------------------------------------------
__global__ void __launch_bounds__(THREADS, 1)
encoder_hmma_kernel(const int* __restrict__ read_count,
                    const int* __restrict__ write_count,
                    const int* __restrict__ fault_count,
                    const int* __restrict__ cow_count,
                    const int* __restrict__ recency,
                    const float* __restrict__ volatility,
                    const float* __restrict__ pressure,
                    const float* __restrict__ count_emb,
                    const float* __restrict__ recency_emb,
                    const float* __restrict__ p_b1,
                    const float* __restrict__ p_b2,
                    const float* __restrict__ v_b1,
                    const float* __restrict__ v_b2,
                    const float* __restrict__ f_wh,
                    const float* __restrict__ f_bh,
                    const float* __restrict__ f_wg,
                    const float* __restrict__ f_bg,
                    const float* __restrict__ ln_g,
                    const float* __restrict__ ln_b,
                    float* __restrict__ out,
                    int num_tiles) {
    extern __shared__ char smraw[];
    float* spar = (float*)(smraw + SM_PAR);
    const uint32_t sbase = smem_u32(smraw);
    const int tid = threadIdx.x;
    const int w   = tid >> 5;          // 0..15
    const int lid = tid & 31;

    // ---- build W fp16 in smem (k-major, 1024B rows, 16B-chunk swizzle) -----
    for (int i = tid; i < 512 * 64; i += THREADS) {
        int n = i >> 6, k = i & 63;
        float wv = 0.0f;
        if (k < 51)       wv = (n < 256) ? f_wh[n * 51 + k] : f_wg[(n - 256) * 51 + k];
        else if (k == 51) wv = (n < 256) ? f_bh[n] : f_bg[n - 256];
        uint32_t off = (uint32_t)k * 1024u + ((((uint32_t)n >> 3) ^ ((uint32_t)k & 7)) << 4)
                       + (((uint32_t)n & 7) << 1);
        *(__half*)(smraw + SM_WH + off) = __float2half_rn(wv);
    }
    for (int i = tid; i < 320; i += THREADS) {
        spar[P_CEMB + i] = count_emb[i];
        spar[P_REMB + i] = recency_emb[i];
    }
    for (int i = tid; i < 848; i += THREADS) spar[P_Q + i] = d_q[i];
    if (tid < 8)  spar[P_SB + tid]      = v_b1[tid];
    if (tid < 6)  spar[P_SB + 8 + tid]  = v_b2[tid];
    if (tid < 24) spar[P_SB + 16 + tid] = p_b1[tid];
    if (tid < 20) spar[P_SB + 40 + tid] = p_b2[tid];
    if (tid < 256) { spar[P_LNG + tid] = ln_g[tid]; spar[P_LNB + tid] = ln_b[tid]; }
    __syncthreads();

    const float* s_q  = spar + P_Q;
    const float* s_sb = spar + P_SB;
    float2* red2  = (float2*)(smraw + SM_RED);
    float2* stat2 = (float2*)(smraw + SM_STAT);
    const float2* lng2 = (const float2*)(spar + P_LNG);
    const float2* lnb2 = (const float2*)(spar + P_LNB);

    const int grp = lid >> 3, li = lid & 7;
    const int r0  = lid >> 2;           // 0..7
    const int cql = (lid & 3) << 1;     // 0,2,4,6

    // ---- register-resident W fragments (once) -------------------------------
    uint32_t Bf[4][8];
#pragma unroll
    for (int c = 0; c < 2; c++) {
        const int chh = w * 2 + c;
        const int chg = 32 + w * 2 + c;
#pragma unroll
        for (int kh = 0; kh < 2; kh++) {
            int krow = kh * 32 + grp * 8 + li;
            uint32_t rowoff = (uint32_t)krow * 1024u;
            uint32_t swh = (((uint32_t)(chh ^ (krow & 7))) << 4);
            uint32_t swg = (((uint32_t)(chg ^ (krow & 7))) << 4);
            ldsm_x4t(&Bf[c][kh * 4],     sbase + SM_WH + rowoff + swh);
            ldsm_x4t(&Bf[2 + c][kh * 4], sbase + SM_WH + rowoff + swg);
        }
    }
    __syncthreads();   // W frags in regs; smem region 0 now the A buffer

    // LN params for this warp's two col-chunks (constant across tiles)
    float2 lg[2][2], lb[2][2];
#pragma unroll
    for (int c = 0; c < 2; c++) {
        const int col = w * 16 + c * 8 + cql;
        lg[c][0] = lng2[col >> 1];
        lb[c][0] = lnb2[col >> 1];
        lg[c][1] = lg[c][0];  // same col for both row-halves
        lb[c][1] = lb[c][0];
    }

    // -------------------- persistent tile loop ------------------------------
    for (int t = blockIdx.x; t < num_tiles; t += gridDim.x) {
        const size_t rowbase = (size_t)t * ROWS_PER_CTA;

        // ---- phase 0: scalar front-end, one row per thread -> A smem -------
        {
            const size_t myrow = rowbase + (size_t)tid;
            const uint32_t abase = (uint32_t)tid * 128u;
            float v8[8];
            auto store_chunk = [&](int j, const float* v) {
                uint32_t hw[4];
#pragma unroll
                for (int q = 0; q < 4; q++) hw[q] = pack2h(v[2 * q], v[2 * q + 1]);
                uint32_t off = abase + (((uint32_t)(j ^ (tid & 7))) << 4);
                *(uint4*)(smraw + SM_A + off) = make_uint4(hw[0], hw[1], hw[2], hw[3]);
            };
            const int rc = read_count[myrow], wc = write_count[myrow];
            const int fc = fault_count[myrow], cc = cow_count[myrow];
            const int rr = recency[myrow];
#pragma unroll
            for (int d = 0; d < 5; d++) v8[d] = spar[P_CEMB + rc * 5 + d];
#pragma unroll
            for (int d = 0; d < 3; d++) v8[5 + d] = spar[P_CEMB + wc * 5 + d];
            store_chunk(0, v8);
            v8[0] = spar[P_CEMB + wc * 5 + 3];
            v8[1] = spar[P_CEMB + wc * 5 + 4];
#pragma unroll
            for (int d = 0; d < 5; d++) v8[2 + d] = spar[P_CEMB + fc * 5 + d];
            v8[7] = spar[P_CEMB + cc * 5 + 0];
            store_chunk(1, v8);
#pragma unroll
            for (int d = 0; d < 4; d++) v8[d] = spar[P_CEMB + cc * 5 + 1 + d];
#pragma unroll
            for (int d = 0; d < 4; d++) v8[4 + d] = spar[P_REMB + rr * 5 + d];
            store_chunk(2, v8);

            float4 v4 = ((const float4*)volatility)[myrow];
            float va[4] = {v4.x, v4.y, v4.z, v4.w};
            float v1[8];
#pragma unroll
            for (int j = 0; j < 8; j++) {
                float a = s_sb[j];
#pragma unroll
                for (int i = 0; i < 4; i++) a = fmaf(s_q[j * 4 + i], va[i], a);
                v1[j] = gelu_exact(a);
            }
            float pv[6];
#pragma unroll
            for (int j = 0; j < 6; j++) {
                float a = s_sb[8 + j];
#pragma unroll
                for (int i = 0; i < 8; i++) a = fmaf(s_q[32 + j * 8 + i], v1[i], a);
                pv[j] = a;
            }
            float4 pA = ((const float4*)pressure)[myrow * 3 + 0];
            float4 pB = ((const float4*)pressure)[myrow * 3 + 1];
            float4 pC = ((const float4*)pressure)[myrow * 3 + 2];
            float pr[12] = {pA.x, pA.y, pA.z, pA.w, pB.x, pB.y, pB.z, pB.w,
                            pC.x, pC.y, pC.z, pC.w};
            float p1[24];
#pragma unroll
            for (int j = 0; j < 24; j++) {
                float a = s_sb[16 + j];
#pragma unroll
                for (int i = 0; i < 12; i++) a = fmaf(s_q[80 + j * 12 + i], pr[i], a);
                p1[j] = gelu_exact(a);
            }
            auto pp = [&](int j) {
                float a = s_sb[40 + j];
#pragma unroll
                for (int i = 0; i < 24; i++) a = fmaf(s_q[368 + j * 24 + i], p1[i], a);
                return a;
            };
            v8[0] = spar[P_REMB + rr * 5 + 4];
#pragma unroll
            for (int d = 0; d < 6; d++) v8[1 + d] = pv[d];
            v8[7] = pp(0);
            store_chunk(3, v8);
#pragma unroll
            for (int d = 0; d < 8; d++) v8[d] = pp(1 + d);
            store_chunk(4, v8);
#pragma unroll
            for (int d = 0; d < 8; d++) v8[d] = pp(9 + d);
            store_chunk(5, v8);
            v8[0] = pp(17); v8[1] = pp(18); v8[2] = pp(19);
            v8[3] = 1.0f; v8[4] = 0.f; v8[5] = 0.f; v8[6] = 0.f; v8[7] = 0.f;
            store_chunk(6, v8);
#pragma unroll
            for (int d = 0; d < 8; d++) v8[d] = 0.f;
            store_chunk(7, v8);
        }
        __syncthreads();   // A ready

        // ---- 8 subtiles of 64 rows: GEMM -> z regs -> stats -> LN store ----
#pragma unroll 1
        for (int sub = 0; sub < 8; sub++) {
            float zreg[32];   // 4 mt x 2 c x 4 vals
#pragma unroll
            for (int mt = 0; mt < 4; mt++) {
                float acc[4][4];
#pragma unroll
                for (int c = 0; c < 4; c++)
#pragma unroll
                    for (int i = 0; i < 4; i++) acc[c][i] = 0.0f;

                const int rloc = sub * SUB_ROWS + mt * 16 + ((grp & 1) << 3) + li;
                const uint32_t roff = (uint32_t)rloc * 128u;
#pragma unroll
                for (int ks = 0; ks < 4; ks++) {
                    uint32_t A[4];
                    const int ch = 2 * ks + (grp >> 1);
                    const uint32_t off = roff + (((uint32_t)(ch ^ (rloc & 7))) << 4);
                    ldsm_x4(A, sbase + SM_A + off);
#pragma unroll
                    for (int c = 0; c < 4; c++)
                        mma16816(acc[c], A, &Bf[c][2 * ks]);
                }
                float s0 = 0.f, q0 = 0.f, s8 = 0.f, q8 = 0.f;
#pragma unroll
                for (int c = 0; c < 2; c++) {
                    float z0 = fast_glu(acc[c][0], acc[2 + c][0]);
                    float z1 = fast_glu(acc[c][1], acc[2 + c][1]);
                    float z2 = fast_glu(acc[c][2], acc[2 + c][2]);
                    float z3 = fast_glu(acc[c][3], acc[2 + c][3]);
                    zreg[mt * 8 + c * 4 + 0] = z0;
                    zreg[mt * 8 + c * 4 + 1] = z1;
                    zreg[mt * 8 + c * 4 + 2] = z2;
                    zreg[mt * 8 + c * 4 + 3] = z3;
                    s0 += z0 + z1;
                    q0 = fmaf(z0, z0, fmaf(z1, z1, q0));
                    s8 += z2 + z3;
                    q8 = fmaf(z2, z2, fmaf(z3, z3, q8));
                }
                s0 += __shfl_xor_sync(0xffffffffu, s0, 1);
                q0 += __shfl_xor_sync(0xffffffffu, q0, 1);
                s8 += __shfl_xor_sync(0xffffffffu, s8, 1);
                q8 += __shfl_xor_sync(0xffffffffu, q8, 1);
                s0 += __shfl_xor_sync(0xffffffffu, s0, 2);
                q0 += __shfl_xor_sync(0xffffffffu, q0, 2);
                s8 += __shfl_xor_sync(0xffffffffu, s8, 2);
                q8 += __shfl_xor_sync(0xffffffffu, q8, 2);
                if ((lid & 3) == 0) {
                    const int zr = mt * 16 + r0;
                    red2[zr * 17 + w]       = make_float2(s0, q0);
                    red2[(zr + 8) * 17 + w] = make_float2(s8, q8);
                }
            }
            __syncthreads();   // red2 ready

            if (tid < SUB_ROWS) {
                float s = 0.f, q = 0.f;
#pragma unroll
                for (int k = 0; k < 16; k++) {
                    float2 p = red2[tid * 17 + k];
                    s += p.x;
                    q += p.y;
                }
                float mu = s * (1.0f / 256.0f);
                float var = fmaxf(q * (1.0f / 256.0f) - mu * mu, 0.0f);
                stat2[tid] = make_float2(mu, rsqrtf(var + 1e-5f));
            }
            __syncthreads();   // stats ready

            // normalize z registers and store directly (coalesced 32B/quad)
#pragma unroll
            for (int mt = 0; mt < 4; mt++) {
                const int lrow = mt * 16 + r0;
                float2 stA = stat2[lrow];
                float2 stB = stat2[lrow + 8];
                const size_t ra = rowbase + (size_t)(sub * SUB_ROWS + lrow);
#pragma unroll
                for (int c = 0; c < 2; c++) {
                    const int col = w * 16 + c * 8 + cql;
                    float z0 = zreg[mt * 8 + c * 4 + 0];
                    float z1 = zreg[mt * 8 + c * 4 + 1];
                    float z2 = zreg[mt * 8 + c * 4 + 2];
                    float z3 = zreg[mt * 8 + c * 4 + 3];
                    float2 o0, o1;
                    o0.x = fmaf((z0 - stA.x) * stA.y, lg[c][0].x, lb[c][0].x);
                    o0.y = fmaf((z1 - stA.x) * stA.y, lg[c][0].y, lb[c][0].y);
                    o1.x = fmaf((z2 - stB.x) * stB.y, lg[c][0].x, lb[c][0].x);
                    o1.y = fmaf((z3 - stB.x) * stB.y, lg[c][0].y, lb[c][0].y);
                    *(float2*)(out + ra * 256 + col)       = o0;
                    *(float2*)(out + (ra + 8) * 256 + col) = o1;
                }
            }
            // no extra sync: red2 writes of next subtile are gated by the
            // stats-ready sync of that subtile; stat2 overwrite gated by
            // red2-ready sync (all stores above precede it in program order).
        }
    }
}

// ---------------------------------------------------------------------------
extern "C" void kernel_launch(void* const* d_in, const int* in_sizes, int n_in,
                              void* d_out, int out_size) {
    const int* read_count  = (const int*)d_in[0];
    const int* write_count = (const int*)d_in[1];
    const int* fault_count = (const int*)d_in[2];
    const int* cow_count   = (const int*)d_in[3];
    const int* recency     = (const int*)d_in[4];
    const float* volatility  = (const float*)d_in[5];
    const float* pressure    = (const float*)d_in[6];
    const float* count_emb   = (const float*)d_in[7];
    const float* recency_emb = (const float*)d_in[8];
    const float* p_w1 = (const float*)d_in[9];
    const float* p_b1 = (const float*)d_in[10];
    const float* p_w2 = (const float*)d_in[11];
    const float* p_b2 = (const float*)d_in[12];
    const float* v_w1 = (const float*)d_in[13];
    const float* v_b1 = (const float*)d_in[14];
    const float* v_w2 = (const float*)d_in[15];
    const float* v_b2 = (const float*)d_in[16];
    const float* f_wh = (const float*)d_in[17];
    const float* f_bh = (const float*)d_in[18];
    const float* f_wg = (const float*)d_in[19];
    const float* f_bg = (const float*)d_in[20];
    const float* ln_g = (const float*)d_in[21];
    const float* ln_b = (const float*)d_in[22];
    float* out = (float*)d_out;

    const int B = in_sizes[0];
    const int num_tiles = B / ROWS_PER_CTA;  // 1024

    int dev = 0, sms = 148;
    cudaGetDevice(&dev);
    cudaDeviceGetAttribute(&sms, cudaDevAttrMultiProcessorCount, dev);
    int grid = num_tiles < sms ? num_tiles : sms;

    quant_prep_kernel<<<4, 512>>>(v_w1, v_w2, p_w1, p_w2);

    cudaFuncSetAttribute(encoder_hmma_kernel,
                         cudaFuncAttributeMaxDynamicSharedMemorySize, SMEM_BYTES);
    encoder_hmma_kernel<<<grid, THREADS, SMEM_BYTES>>>(
        read_count, write_count, fault_count, cow_count, recency,
        volatility, pressure, count_emb, recency_emb,
        p_b1, p_b2, v_b1, v_b2,
        f_wh, f_bh, f_wg, f_bg, ln_g, ln_b, out, num_tiles);
}